// round 2
// baseline (speedup 1.0000x reference)
#include <cuda_runtime.h>
#include <cstdint>
#include <cstddef>

// Problem constants
#define BB 2
#define TT 2048
#define CC 1024
#define HH 16
#define DD 64
#define MTOT (BB*TT)          // 4096 rows

// ---------------------------------------------------------------------------
// Scratch (device globals: allocation-free rule). Referenced directly from
// device code — no cudaGetSymbolAddress needed in kernel_launch.
// ---------------------------------------------------------------------------
__device__ float g_qkv[(size_t)MTOT * 3 * CC];  // [4096, 3072]  Q|K|V packed
__device__ float g_att[(size_t)MTOT * CC];      // [4096, 1024]  attention out

// ---------------------------------------------------------------------------
// Helpers
// ---------------------------------------------------------------------------
__device__ __forceinline__ float to_tf32(float x) {
    uint32_t y;
    asm("cvt.rna.tf32.f32 %0, %1;" : "=r"(y) : "f"(x));
    return __uint_as_float(y);
}

// D += A(16x8) * B(8x8), tf32, fp32 accum. Accumulate in place.
__device__ __forceinline__ void mma8(float d[4], const uint32_t a[4],
                                     uint32_t b0, uint32_t b1) {
    asm volatile(
        "mma.sync.aligned.m16n8k8.row.col.f32.tf32.tf32.f32 "
        "{%0,%1,%2,%3}, {%4,%5,%6,%7}, {%8,%9}, {%0,%1,%2,%3};\n"
        : "+f"(d[0]), "+f"(d[1]), "+f"(d[2]), "+f"(d[3])
        : "r"(a[0]), "r"(a[1]), "r"(a[2]), "r"(a[3]), "r"(b0), "r"(b1));
}

// ---------------------------------------------------------------------------
// Generic tf32 GEMM body:  C[M,N] = A[M,K] @ B[K,N] (+ bias[N])
// Row-major everywhere. M%128==0, N%128==0, K%32==0 assumed.
// Block tile 128x128, BK=32, 256 threads (8 warps as 4(m) x 2(n), 32x64 each).
// ---------------------------------------------------------------------------
#define GBM 128
#define GBN 128
#define GBK 32
#define APITCH 36    // odd-bank pitch: conflict-free A frag loads
#define BPITCH 136   // conflict-free B frag loads

__device__ __forceinline__ void
gemm_tf32_body(const float* __restrict__ A, const float* __restrict__ Bm,
               const float* __restrict__ bias, float* __restrict__ C,
               int M, int N, int K)
{
    __shared__ float As[GBM][APITCH];
    __shared__ float Bs[GBK][BPITCH];

    const int tid  = threadIdx.x;
    const int bm   = blockIdx.y;
    const int bn   = blockIdx.x;
    const int warp = tid >> 5;
    const int lane = tid & 31;
    const int wm   = warp & 3;       // 0..3  (m direction)
    const int wn   = warp >> 2;      // 0..1  (n direction)
    const int g    = lane >> 2;      // groupID 0..7
    const int tir  = lane & 3;       // thread-in-group 0..3

    float acc[2][8][4];
#pragma unroll
    for (int mt = 0; mt < 2; mt++)
#pragma unroll
        for (int nt = 0; nt < 8; nt++)
#pragma unroll
            for (int i = 0; i < 4; i++) acc[mt][nt][i] = 0.0f;

    const float* Ablk = A + (size_t)(bm * GBM) * K;
    const float* Bblk = Bm + (size_t)bn * GBN;

    for (int k0 = 0; k0 < K; k0 += GBK) {
        // ---- stage A tile: 128x32 = 1024 float4, 4 per thread ----
#pragma unroll
        for (int t = 0; t < 4; t++) {
            int f   = tid + t * 256;
            int row = f >> 3;          // 0..127
            int c4  = f & 7;           // 0..7
            float4 v = *(const float4*)(Ablk + (size_t)row * K + k0 + c4 * 4);
            float* dst = &As[row][c4 * 4];
            dst[0] = to_tf32(v.x); dst[1] = to_tf32(v.y);
            dst[2] = to_tf32(v.z); dst[3] = to_tf32(v.w);
        }
        // ---- stage B tile: 32x128 = 1024 float4, 4 per thread ----
#pragma unroll
        for (int t = 0; t < 4; t++) {
            int f   = tid + t * 256;
            int row = f >> 5;          // 0..31
            int c4  = f & 31;          // 0..31
            float4 v = *(const float4*)(Bblk + (size_t)(k0 + row) * N + c4 * 4);
            float* dst = &Bs[row][c4 * 4];
            dst[0] = to_tf32(v.x); dst[1] = to_tf32(v.y);
            dst[2] = to_tf32(v.z); dst[3] = to_tf32(v.w);
        }
        __syncthreads();

#pragma unroll
        for (int kk = 0; kk < 4; kk++) {
            const int kb = kk * 8;
            uint32_t a[2][4];
#pragma unroll
            for (int mt = 0; mt < 2; mt++) {
                const int r = wm * 32 + mt * 16;
                a[mt][0] = __float_as_uint(As[r + g    ][kb + tir    ]);
                a[mt][1] = __float_as_uint(As[r + g + 8][kb + tir    ]);
                a[mt][2] = __float_as_uint(As[r + g    ][kb + tir + 4]);
                a[mt][3] = __float_as_uint(As[r + g + 8][kb + tir + 4]);
            }
#pragma unroll
            for (int nt = 0; nt < 8; nt++) {
                const int cn = wn * 64 + nt * 8 + g;
                uint32_t b0 = __float_as_uint(Bs[kb + tir    ][cn]);
                uint32_t b1 = __float_as_uint(Bs[kb + tir + 4][cn]);
                mma8(acc[0][nt], a[0], b0, b1);
                mma8(acc[1][nt], a[1], b0, b1);
            }
        }
        __syncthreads();
    }

    // ---- epilogue ----
#pragma unroll
    for (int mt = 0; mt < 2; mt++) {
#pragma unroll
        for (int nt = 0; nt < 8; nt++) {
            int row = bm * GBM + wm * 32 + mt * 16 + g;
            int col = bn * GBN + wn * 64 + nt * 8 + tir * 2;
            float bb0 = 0.f, bb1 = 0.f;
            if (bias) { bb0 = bias[col]; bb1 = bias[col + 1]; }
            float2 v0 = make_float2(acc[mt][nt][0] + bb0, acc[mt][nt][1] + bb1);
            float2 v1 = make_float2(acc[mt][nt][2] + bb0, acc[mt][nt][3] + bb1);
            *(float2*)(C + (size_t)row * N + col)       = v0;
            *(float2*)(C + (size_t)(row + 8) * N + col) = v1;
        }
    }
}

// Wrappers binding the device-global scratch (avoids cudaGetSymbolAddress).
__global__ void __launch_bounds__(256)
gemm_qkv_kernel(const float* __restrict__ x, const float* __restrict__ w_qkv)
{
    gemm_tf32_body(x, w_qkv, nullptr, g_qkv, MTOT, 3 * CC, CC);
}

__global__ void __launch_bounds__(256)
gemm_proj_kernel(const float* __restrict__ w_proj,
                 const float* __restrict__ b_proj, float* __restrict__ out)
{
    gemm_tf32_body(g_att, w_proj, b_proj, out, MTOT, CC, CC);
}

// ---------------------------------------------------------------------------
// Flash attention (causal), tf32 mma.
// grid = (T/64, B*H). Each CTA: 64 q-rows, loops over <=qb+1 k-blocks of 64.
// 4 warps; warp w owns q-rows [w*16, w*16+16).
// smem (dynamic): Qs, Ks, Vs, Ps — each [64][68] floats (pitch 68 => bank-clean
// A-fragment loads). Total 69632 B.
// ---------------------------------------------------------------------------
#define FP 68
#define FLASH_SMEM (4 * 64 * FP * 4)

__global__ void __launch_bounds__(128)
flash_kernel()
{
    extern __shared__ float fsm[];
    float* Qs = fsm;
    float* Ks = fsm + 64 * FP;
    float* Vs = fsm + 2 * 64 * FP;
    float* Ps = fsm + 3 * 64 * FP;

    const float* qkv = g_qkv;
    float* O = g_att;

    const int qb  = (gridDim.x - 1) - blockIdx.x;   // heavy blocks launch first
    const int bh  = blockIdx.y;
    const int b   = bh >> 4;
    const int h   = bh & 15;
    const int tid = threadIdx.x;
    const int w   = tid >> 5;
    const int lane = tid & 31;
    const int g   = lane >> 2;
    const int tir = lane & 3;

    const float scale = 0.125f;   // 1/sqrt(64), exact power of two
    const size_t rowstride = 3 * CC;       // 3072
    const float* qbase = qkv + (size_t)(b * TT) * rowstride + h * DD;
    const float* kbase = qbase + CC;
    const float* vbase = qbase + 2 * CC;

    // ---- load Q tile once (pre-scaled, tf32) ----
#pragma unroll
    for (int t = 0; t < 8; t++) {
        int f   = tid + t * 128;
        int row = f >> 4;         // 0..63
        int c4  = f & 15;         // 0..15
        float4 v = *(const float4*)(qbase + (size_t)(qb * 64 + row) * rowstride + c4 * 4);
        float* dst = &Qs[row * FP + c4 * 4];
        dst[0] = to_tf32(v.x * scale); dst[1] = to_tf32(v.y * scale);
        dst[2] = to_tf32(v.z * scale); dst[3] = to_tf32(v.w * scale);
    }

    float m0 = -1e30f, m1 = -1e30f;
    float l0 = 0.f, l1 = 0.f;
    float o[8][4];
#pragma unroll
    for (int nt = 0; nt < 8; nt++)
#pragma unroll
        for (int i = 0; i < 4; i++) o[nt][i] = 0.f;

    for (int j = 0; j <= qb; j++) {
        __syncthreads();   // protect Ks/Vs against readers from previous iter
        // ---- stage K,V tiles ----
#pragma unroll
        for (int t = 0; t < 8; t++) {
            int f   = tid + t * 128;
            int row = f >> 4;
            int c4  = f & 15;
            size_t goff = (size_t)(j * 64 + row) * rowstride + c4 * 4;
            float4 kv = *(const float4*)(kbase + goff);
            float4 vv = *(const float4*)(vbase + goff);
            float* kd = &Ks[row * FP + c4 * 4];
            kd[0] = to_tf32(kv.x); kd[1] = to_tf32(kv.y);
            kd[2] = to_tf32(kv.z); kd[3] = to_tf32(kv.w);
            float* vd = &Vs[row * FP + c4 * 4];
            vd[0] = to_tf32(vv.x); vd[1] = to_tf32(vv.y);
            vd[2] = to_tf32(vv.z); vd[3] = to_tf32(vv.w);
        }
        __syncthreads();

        // ---- S = (Q*scale) @ K^T : warp computes 16x64 ----
        float s[8][4];
#pragma unroll
        for (int nt = 0; nt < 8; nt++)
#pragma unroll
            for (int i = 0; i < 4; i++) s[nt][i] = 0.f;

#pragma unroll
        for (int kk = 0; kk < 8; kk++) {
            const int kb = kk * 8;
            const int r  = w * 16;
            uint32_t a[4];
            a[0] = __float_as_uint(Qs[(r + g    ) * FP + kb + tir    ]);
            a[1] = __float_as_uint(Qs[(r + g + 8) * FP + kb + tir    ]);
            a[2] = __float_as_uint(Qs[(r + g    ) * FP + kb + tir + 4]);
            a[3] = __float_as_uint(Qs[(r + g + 8) * FP + kb + tir + 4]);
#pragma unroll
            for (int nt = 0; nt < 8; nt++) {
                uint32_t b0 = __float_as_uint(Ks[(nt * 8 + g) * FP + kb + tir    ]);
                uint32_t b1 = __float_as_uint(Ks[(nt * 8 + g) * FP + kb + tir + 4]);
                mma8(s[nt], a, b0, b1);
            }
        }

        // ---- causal mask (diagonal block only) ----
        if (j == qb) {
            const int qr0 = w * 16 + g;
            const int qr1 = qr0 + 8;
#pragma unroll
            for (int nt = 0; nt < 8; nt++) {
                int c0 = nt * 8 + tir * 2;
                int c1 = c0 + 1;
                if (c0 > qr0) s[nt][0] = -1e30f;
                if (c1 > qr0) s[nt][1] = -1e30f;
                if (c0 > qr1) s[nt][2] = -1e30f;
                if (c1 > qr1) s[nt][3] = -1e30f;
            }
        }

        // ---- online softmax ----
        float rm0 = -1e30f, rm1 = -1e30f;
#pragma unroll
        for (int nt = 0; nt < 8; nt++) {
            rm0 = fmaxf(rm0, fmaxf(s[nt][0], s[nt][1]));
            rm1 = fmaxf(rm1, fmaxf(s[nt][2], s[nt][3]));
        }
        rm0 = fmaxf(rm0, __shfl_xor_sync(0xffffffffu, rm0, 1));
        rm0 = fmaxf(rm0, __shfl_xor_sync(0xffffffffu, rm0, 2));
        rm1 = fmaxf(rm1, __shfl_xor_sync(0xffffffffu, rm1, 1));
        rm1 = fmaxf(rm1, __shfl_xor_sync(0xffffffffu, rm1, 2));

        float nm0 = fmaxf(m0, rm0), nm1 = fmaxf(m1, rm1);
        float cf0 = __expf(m0 - nm0), cf1 = __expf(m1 - nm1);
        m0 = nm0; m1 = nm1;

        float rs0 = 0.f, rs1 = 0.f;
        const int prow = w * 16 + g;
#pragma unroll
        for (int nt = 0; nt < 8; nt++) {
            int c = nt * 8 + tir * 2;
            float p0 = __expf(s[nt][0] - nm0);
            float p1 = __expf(s[nt][1] - nm0);
            float p2 = __expf(s[nt][2] - nm1);
            float p3 = __expf(s[nt][3] - nm1);
            rs0 += p0 + p1;
            rs1 += p2 + p3;
            Ps[(prow    ) * FP + c    ] = to_tf32(p0);
            Ps[(prow    ) * FP + c + 1] = to_tf32(p1);
            Ps[(prow + 8) * FP + c    ] = to_tf32(p2);
            Ps[(prow + 8) * FP + c + 1] = to_tf32(p3);
        }
        rs0 += __shfl_xor_sync(0xffffffffu, rs0, 1);
        rs0 += __shfl_xor_sync(0xffffffffu, rs0, 2);
        rs1 += __shfl_xor_sync(0xffffffffu, rs1, 1);
        rs1 += __shfl_xor_sync(0xffffffffu, rs1, 2);
        l0 = l0 * cf0 + rs0;
        l1 = l1 * cf1 + rs1;

        // rescale accumulator
#pragma unroll
        for (int nt = 0; nt < 8; nt++) {
            o[nt][0] *= cf0; o[nt][1] *= cf0;
            o[nt][2] *= cf1; o[nt][3] *= cf1;
        }

        __syncwarp();   // Ps rows are per-warp private; just order the writes

        // ---- O += P @ V ----
#pragma unroll
        for (int kk = 0; kk < 8; kk++) {
            const int kb = kk * 8;
            const int r  = w * 16;
            uint32_t a[4];
            a[0] = __float_as_uint(Ps[(r + g    ) * FP + kb + tir    ]);
            a[1] = __float_as_uint(Ps[(r + g + 8) * FP + kb + tir    ]);
            a[2] = __float_as_uint(Ps[(r + g    ) * FP + kb + tir + 4]);
            a[3] = __float_as_uint(Ps[(r + g + 8) * FP + kb + tir + 4]);
#pragma unroll
            for (int nt = 0; nt < 8; nt++) {
                uint32_t b0 = __float_as_uint(Vs[(kb + tir    ) * FP + nt * 8 + g]);
                uint32_t b1 = __float_as_uint(Vs[(kb + tir + 4) * FP + nt * 8 + g]);
                mma8(o[nt], a, b0, b1);
            }
        }
    }

    // ---- normalize and write O in [B,T,C] layout ----
    const float inv0 = 1.f / l0;
    const float inv1 = 1.f / l1;
    const int t0 = qb * 64 + w * 16 + g;
#pragma unroll
    for (int nt = 0; nt < 8; nt++) {
        int d = nt * 8 + tir * 2;
        float2 v0 = make_float2(o[nt][0] * inv0, o[nt][1] * inv0);
        float2 v1 = make_float2(o[nt][2] * inv1, o[nt][3] * inv1);
        *(float2*)(O + (size_t)(b * TT + t0    ) * CC + h * DD + d) = v0;
        *(float2*)(O + (size_t)(b * TT + t0 + 8) * CC + h * DD + d) = v1;
    }
}

// ---------------------------------------------------------------------------
// Launch
// ---------------------------------------------------------------------------
extern "C" void kernel_launch(void* const* d_in, const int* in_sizes, int n_in,
                              void* d_out, int out_size)
{
    const float* x      = (const float*)d_in[0];
    const float* w_qkv  = (const float*)d_in[1];
    const float* w_proj = (const float*)d_in[2];
    const float* b_proj = (const float*)d_in[3];
    float* out = (float*)d_out;

    cudaFuncSetAttribute(flash_kernel,
                         cudaFuncAttributeMaxDynamicSharedMemorySize, FLASH_SMEM);

    // 1) QKV projection: [4096,1024] @ [1024,3072]
    gemm_qkv_kernel<<<dim3(3 * CC / GBN, MTOT / GBM), 256>>>(x, w_qkv);

    // 2) Fused causal flash attention
    flash_kernel<<<dim3(TT / 64, BB * HH), 128, FLASH_SMEM>>>();

    // 3) Output projection + bias: [4096,1024] @ [1024,1024]
    gemm_proj_kernel<<<dim3(CC / GBN, MTOT / GBM), 256>>>(w_proj, b_proj, out);
}

// round 4
// speedup vs baseline: 1.0172x; 1.0172x over previous
#include <cuda_runtime.h>
#include <cstdint>
#include <cstddef>

// Problem constants
#define BB 2
#define TT 2048
#define CC 1024
#define HH 16
#define DD 64
#define MTOT (BB*TT)          // 4096 rows

// ---------------------------------------------------------------------------
// Scratch (device globals: allocation-free rule)
// ---------------------------------------------------------------------------
__device__ float g_qkv[(size_t)MTOT * 3 * CC];  // [4096, 3072]  Q|K|V packed
__device__ float g_att[(size_t)MTOT * CC];      // [4096, 1024]  attention out

// ---------------------------------------------------------------------------
// Helpers
// ---------------------------------------------------------------------------
__device__ __forceinline__ float to_tf32(float x) {
    uint32_t y;
    asm("cvt.rna.tf32.f32 %0, %1;" : "=r"(y) : "f"(x));
    return __uint_as_float(y);
}
__device__ __forceinline__ uint32_t to_tf32u(float x) {
    uint32_t y;
    asm("cvt.rna.tf32.f32 %0, %1;" : "=r"(y) : "f"(x));
    return y;
}

// D += A(16x8) * B(8x8), tf32, fp32 accum. Accumulate in place.
__device__ __forceinline__ void mma8(float d[4], const uint32_t a[4],
                                     uint32_t b0, uint32_t b1) {
    asm volatile(
        "mma.sync.aligned.m16n8k8.row.col.f32.tf32.tf32.f32 "
        "{%0,%1,%2,%3}, {%4,%5,%6,%7}, {%8,%9}, {%0,%1,%2,%3};\n"
        : "+f"(d[0]), "+f"(d[1]), "+f"(d[2]), "+f"(d[3])
        : "r"(a[0]), "r"(a[1]), "r"(a[2]), "r"(a[3]), "r"(b0), "r"(b1));
}

// cp.async 16B
__device__ __forceinline__ void cp_async16(float* smem_dst, const float* gsrc) {
    uint32_t s = (uint32_t)__cvta_generic_to_shared(smem_dst);
    asm volatile("cp.async.cg.shared.global [%0], [%1], 16;\n"
                 :: "r"(s), "l"(gsrc) : "memory");
}
#define CP_COMMIT() asm volatile("cp.async.commit_group;\n" ::: "memory")
#define CP_WAIT0()  asm volatile("cp.async.wait_group 0;\n" ::: "memory")

// ---------------------------------------------------------------------------
// tf32 GEMM, cp.async 2-stage double buffered.
// C[M,N] = A[M,K] @ B[K,N] (+bias). Block tile 128x128, BK=32, 256 threads.
// ---------------------------------------------------------------------------
#define GBM 128
#define GBN 128
#define GBK 32
#define APITCH 36     // words; 144B rows (16B-aligned, conflict-free A frags)
#define BPITCH 136    // words; 544B rows (conflict-free B frags)
#define ASTG (GBM*APITCH)   // 4608 floats per stage
#define BSTG (GBK*BPITCH)   // 4352 floats per stage
#define GEMM_SMEM ((2*(ASTG+BSTG))*4)   // 71680 B

__device__ __forceinline__ void
gemm_stage(const float* __restrict__ Ablk, const float* __restrict__ Bblk,
           int N, int K, int k0, float* As, float* Bs, int tid)
{
#pragma unroll
    for (int t = 0; t < 4; t++) {
        int f = tid + t * 256;
        int row = f >> 3, c4 = f & 7;
        cp_async16(As + row * APITCH + c4 * 4,
                   Ablk + (size_t)row * K + k0 + c4 * 4);
    }
#pragma unroll
    for (int t = 0; t < 4; t++) {
        int f = tid + t * 256;
        int row = f >> 5, c4 = f & 31;
        cp_async16(Bs + row * BPITCH + c4 * 4,
                   Bblk + (size_t)(k0 + row) * N + c4 * 4);
    }
}

__device__ __forceinline__ void
gemm_tf32_body(const float* __restrict__ A, const float* __restrict__ Bm,
               const float* __restrict__ bias, float* __restrict__ C,
               int M, int N, int K)
{
    extern __shared__ float sm[];
    float* As = sm;                 // 2 stages of ASTG
    float* Bs = sm + 2 * ASTG;      // 2 stages of BSTG

    const int tid  = threadIdx.x;
    const int bm   = blockIdx.y;
    const int bn   = blockIdx.x;
    const int warp = tid >> 5;
    const int lane = tid & 31;
    const int wm   = warp & 3;
    const int wn   = warp >> 2;
    const int g    = lane >> 2;
    const int tir  = lane & 3;

    float acc[2][8][4];
#pragma unroll
    for (int mt = 0; mt < 2; mt++)
#pragma unroll
        for (int nt = 0; nt < 8; nt++)
#pragma unroll
            for (int i = 0; i < 4; i++) acc[mt][nt][i] = 0.0f;

    const float* Ablk = A + (size_t)(bm * GBM) * K;
    const float* Bblk = Bm + (size_t)bn * GBN;
    const int NT = K / GBK;

    gemm_stage(Ablk, Bblk, N, K, 0, As, Bs, tid);
    CP_COMMIT();

    for (int it = 0; it < NT; it++) {
        CP_WAIT0();
        __syncthreads();
        if (it + 1 < NT) {
            int nb = (it + 1) & 1;
            gemm_stage(Ablk, Bblk, N, K, (it + 1) * GBK,
                       As + nb * ASTG, Bs + nb * BSTG, tid);
            CP_COMMIT();
        }
        const float* Ac = As + (it & 1) * ASTG;
        const float* Bc = Bs + (it & 1) * BSTG;

#pragma unroll
        for (int kk = 0; kk < 4; kk++) {
            const int kb = kk * 8;
            uint32_t a[2][4];
#pragma unroll
            for (int mt = 0; mt < 2; mt++) {
                const int r = wm * 32 + mt * 16;
                a[mt][0] = to_tf32u(Ac[(r + g    ) * APITCH + kb + tir    ]);
                a[mt][1] = to_tf32u(Ac[(r + g + 8) * APITCH + kb + tir    ]);
                a[mt][2] = to_tf32u(Ac[(r + g    ) * APITCH + kb + tir + 4]);
                a[mt][3] = to_tf32u(Ac[(r + g + 8) * APITCH + kb + tir + 4]);
            }
#pragma unroll
            for (int nt = 0; nt < 8; nt++) {
                const int cn = wn * 64 + nt * 8 + g;
                uint32_t b0 = to_tf32u(Bc[(kb + tir    ) * BPITCH + cn]);
                uint32_t b1 = to_tf32u(Bc[(kb + tir + 4) * BPITCH + cn]);
                mma8(acc[0][nt], a[0], b0, b1);
                mma8(acc[1][nt], a[1], b0, b1);
            }
        }
        __syncthreads();
    }

    // ---- epilogue ----
#pragma unroll
    for (int mt = 0; mt < 2; mt++) {
#pragma unroll
        for (int nt = 0; nt < 8; nt++) {
            int row = bm * GBM + wm * 32 + mt * 16 + g;
            int col = bn * GBN + wn * 64 + nt * 8 + tir * 2;
            float bb0 = 0.f, bb1 = 0.f;
            if (bias) { bb0 = bias[col]; bb1 = bias[col + 1]; }
            float2 v0 = make_float2(acc[mt][nt][0] + bb0, acc[mt][nt][1] + bb1);
            float2 v1 = make_float2(acc[mt][nt][2] + bb0, acc[mt][nt][3] + bb1);
            *(float2*)(C + (size_t)row * N + col)       = v0;
            *(float2*)(C + (size_t)(row + 8) * N + col) = v1;
        }
    }
}

__global__ void __launch_bounds__(256, 2)
gemm_qkv_kernel(const float* __restrict__ x, const float* __restrict__ w_qkv)
{
    gemm_tf32_body(x, w_qkv, nullptr, g_qkv, MTOT, 3 * CC, CC);
}

__global__ void __launch_bounds__(256, 2)
gemm_proj_kernel(const float* __restrict__ w_proj,
                 const float* __restrict__ b_proj, float* __restrict__ out)
{
    gemm_tf32_body(g_att, w_proj, b_proj, out, MTOT, CC, CC);
}

// ---------------------------------------------------------------------------
// Flash attention (causal), tf32 mma, cp.async 2-stage K/V double buffer.
// grid = (T/128, B*H). CTA: 128 q-rows, 8 warps (warp w owns rows w*16..+16),
// iterates k-blocks of 64 (jmax = 2*qb+1).
// smem: Qs[128][68], Ps[128][68], Ks[2][64][68], Vs[2][64][72].
// ---------------------------------------------------------------------------
#define FP 68
#define VP 72
#define KSTG (64*FP)
#define VSTG (64*VP)
#define FLASH_SMEM ((2*128*FP + 2*KSTG + 2*VSTG)*4)   // 141312 B

__global__ void __launch_bounds__(256)
flash_kernel()
{
    extern __shared__ float fsm[];
    float* Qs = fsm;
    float* Ps = fsm + 128 * FP;
    float* Ks = fsm + 2 * 128 * FP;
    float* Vs = Ks + 2 * KSTG;

    const float* qkv = g_qkv;
    float* O = g_att;

    const int qb  = (gridDim.x - 1) - blockIdx.x;   // heavy blocks first
    const int bh  = blockIdx.y;
    const int b   = bh >> 4;
    const int h   = bh & 15;
    const int tid = threadIdx.x;
    const int w   = tid >> 5;
    const int lane = tid & 31;
    const int g   = lane >> 2;
    const int tir = lane & 3;

    const float scale = 0.125f;            // 1/sqrt(64)
    const size_t rowstride = 3 * CC;       // 3072
    const float* qbase = qkv + (size_t)(b * TT) * rowstride + h * DD;
    const float* kbase = qbase + CC;
    const float* vbase = qbase + 2 * CC;

    const int jmax = 2 * qb + 1;

    // ---- prefetch K/V block 0 (cp.async) ----
#pragma unroll
    for (int t = 0; t < 4; t++) {
        int f = tid + t * 256;
        int row = f >> 4, c4 = f & 15;
        size_t goff = (size_t)row * rowstride + c4 * 4;
        cp_async16(Ks + row * FP + c4 * 4, kbase + goff);
        cp_async16(Vs + row * VP + c4 * 4, vbase + goff);
    }
    CP_COMMIT();

    // ---- load Q tile (128x64), pre-scaled, tf32 ----
#pragma unroll
    for (int t = 0; t < 8; t++) {
        int f   = tid + t * 256;
        int row = f >> 4;          // 0..127
        int c4  = f & 15;          // 0..15
        float4 v = *(const float4*)(qbase + (size_t)(qb * 128 + row) * rowstride + c4 * 4);
        float* dst = &Qs[row * FP + c4 * 4];
        dst[0] = to_tf32(v.x * scale); dst[1] = to_tf32(v.y * scale);
        dst[2] = to_tf32(v.z * scale); dst[3] = to_tf32(v.w * scale);
    }

    float m0 = -1e30f, m1 = -1e30f;
    float l0 = 0.f, l1 = 0.f;
    float o[8][4];
#pragma unroll
    for (int nt = 0; nt < 8; nt++)
#pragma unroll
        for (int i = 0; i < 4; i++) o[nt][i] = 0.f;

    for (int j = 0; j <= jmax; j++) {
        CP_WAIT0();
        __syncthreads();
        if (j + 1 <= jmax) {
            int nb = (j + 1) & 1;
#pragma unroll
            for (int t = 0; t < 4; t++) {
                int f = tid + t * 256;
                int row = f >> 4, c4 = f & 15;
                size_t goff = (size_t)((j + 1) * 64 + row) * rowstride + c4 * 4;
                cp_async16(Ks + nb * KSTG + row * FP + c4 * 4, kbase + goff);
                cp_async16(Vs + nb * VSTG + row * VP + c4 * 4, vbase + goff);
            }
            CP_COMMIT();
        }
        const float* Kc = Ks + (j & 1) * KSTG;
        const float* Vc = Vs + (j & 1) * VSTG;

        // ---- S = (Q*scale) @ K^T : warp computes 16x64 ----
        float s[8][4];
#pragma unroll
        for (int nt = 0; nt < 8; nt++)
#pragma unroll
            for (int i = 0; i < 4; i++) s[nt][i] = 0.f;

#pragma unroll
        for (int kk = 0; kk < 8; kk++) {
            const int kb = kk * 8;
            const int r  = w * 16;
            uint32_t a[4];
            a[0] = __float_as_uint(Qs[(r + g    ) * FP + kb + tir    ]);
            a[1] = __float_as_uint(Qs[(r + g + 8) * FP + kb + tir    ]);
            a[2] = __float_as_uint(Qs[(r + g    ) * FP + kb + tir + 4]);
            a[3] = __float_as_uint(Qs[(r + g + 8) * FP + kb + tir + 4]);
#pragma unroll
            for (int nt = 0; nt < 8; nt++) {
                uint32_t b0 = to_tf32u(Kc[(nt * 8 + g) * FP + kb + tir    ]);
                uint32_t b1 = to_tf32u(Kc[(nt * 8 + g) * FP + kb + tir + 4]);
                mma8(s[nt], a, b0, b1);
            }
        }

        // ---- causal mask (only needed for the two diagonal-region blocks) ----
        if (j >= 2 * qb) {
            const int qr0 = qb * 128 + w * 16 + g;
            const int qr1 = qr0 + 8;
            const int jc  = j * 64;
#pragma unroll
            for (int nt = 0; nt < 8; nt++) {
                int c0 = jc + nt * 8 + tir * 2;
                int c1 = c0 + 1;
                if (c0 > qr0) s[nt][0] = -1e30f;
                if (c1 > qr0) s[nt][1] = -1e30f;
                if (c0 > qr1) s[nt][2] = -1e30f;
                if (c1 > qr1) s[nt][3] = -1e30f;
            }
        }

        // ---- online softmax ----
        float rm0 = -1e30f, rm1 = -1e30f;
#pragma unroll
        for (int nt = 0; nt < 8; nt++) {
            rm0 = fmaxf(rm0, fmaxf(s[nt][0], s[nt][1]));
            rm1 = fmaxf(rm1, fmaxf(s[nt][2], s[nt][3]));
        }
        rm0 = fmaxf(rm0, __shfl_xor_sync(0xffffffffu, rm0, 1));
        rm0 = fmaxf(rm0, __shfl_xor_sync(0xffffffffu, rm0, 2));
        rm1 = fmaxf(rm1, __shfl_xor_sync(0xffffffffu, rm1, 1));
        rm1 = fmaxf(rm1, __shfl_xor_sync(0xffffffffu, rm1, 2));

        float nm0 = fmaxf(m0, rm0), nm1 = fmaxf(m1, rm1);
        float cf0 = __expf(m0 - nm0), cf1 = __expf(m1 - nm1);
        m0 = nm0; m1 = nm1;

        float rs0 = 0.f, rs1 = 0.f;
        const int prow = w * 16 + g;
#pragma unroll
        for (int nt = 0; nt < 8; nt++) {
            int c = nt * 8 + tir * 2;
            float p0 = __expf(s[nt][0] - nm0);
            float p1 = __expf(s[nt][1] - nm0);
            float p2 = __expf(s[nt][2] - nm1);
            float p3 = __expf(s[nt][3] - nm1);
            rs0 += p0 + p1;
            rs1 += p2 + p3;
            *(float2*)&Ps[(prow    ) * FP + c] =
                make_float2(to_tf32(p0), to_tf32(p1));
            *(float2*)&Ps[(prow + 8) * FP + c] =
                make_float2(to_tf32(p2), to_tf32(p3));
        }
        rs0 += __shfl_xor_sync(0xffffffffu, rs0, 1);
        rs0 += __shfl_xor_sync(0xffffffffu, rs0, 2);
        rs1 += __shfl_xor_sync(0xffffffffu, rs1, 1);
        rs1 += __shfl_xor_sync(0xffffffffu, rs1, 2);
        l0 = l0 * cf0 + rs0;
        l1 = l1 * cf1 + rs1;

#pragma unroll
        for (int nt = 0; nt < 8; nt++) {
            o[nt][0] *= cf0; o[nt][1] *= cf0;
            o[nt][2] *= cf1; o[nt][3] *= cf1;
        }

        __syncwarp();   // Ps rows are per-warp private; order writes vs reads

        // ---- O += P @ V ----
#pragma unroll
        for (int kk = 0; kk < 8; kk++) {
            const int kb = kk * 8;
            const int r  = w * 16;
            uint32_t a[4];
            a[0] = __float_as_uint(Ps[(r + g    ) * FP + kb + tir    ]);
            a[1] = __float_as_uint(Ps[(r + g + 8) * FP + kb + tir    ]);
            a[2] = __float_as_uint(Ps[(r + g    ) * FP + kb + tir + 4]);
            a[3] = __float_as_uint(Ps[(r + g + 8) * FP + kb + tir + 4]);
#pragma unroll
            for (int nt = 0; nt < 8; nt++) {
                uint32_t b0 = to_tf32u(Vc[(kb + tir    ) * VP + nt * 8 + g]);
                uint32_t b1 = to_tf32u(Vc[(kb + tir + 4) * VP + nt * 8 + g]);
                mma8(o[nt], a, b0, b1);
            }
        }
        __syncthreads();
    }

    // ---- normalize and write O in [B,T,C] layout ----
    const float inv0 = 1.f / l0;
    const float inv1 = 1.f / l1;
    const int t0 = qb * 128 + w * 16 + g;
#pragma unroll
    for (int nt = 0; nt < 8; nt++) {
        int d = nt * 8 + tir * 2;
        float2 v0 = make_float2(o[nt][0] * inv0, o[nt][1] * inv0);
        float2 v1 = make_float2(o[nt][2] * inv1, o[nt][3] * inv1);
        *(float2*)(O + (size_t)(b * TT + t0    ) * CC + h * DD + d) = v0;
        *(float2*)(O + (size_t)(b * TT + t0 + 8) * CC + h * DD + d) = v1;
    }
}

// ---------------------------------------------------------------------------
// Launch
// ---------------------------------------------------------------------------
extern "C" void kernel_launch(void* const* d_in, const int* in_sizes, int n_in,
                              void* d_out, int out_size)
{
    const float* x      = (const float*)d_in[0];
    const float* w_qkv  = (const float*)d_in[1];
    const float* w_proj = (const float*)d_in[2];
    const float* b_proj = (const float*)d_in[3];
    float* out = (float*)d_out;

    cudaFuncSetAttribute(gemm_qkv_kernel,
                         cudaFuncAttributeMaxDynamicSharedMemorySize, GEMM_SMEM);
    cudaFuncSetAttribute(gemm_proj_kernel,
                         cudaFuncAttributeMaxDynamicSharedMemorySize, GEMM_SMEM);
    cudaFuncSetAttribute(flash_kernel,
                         cudaFuncAttributeMaxDynamicSharedMemorySize, FLASH_SMEM);

    // 1) QKV projection: [4096,1024] @ [1024,3072]
    gemm_qkv_kernel<<<dim3(3 * CC / GBN, MTOT / GBM), 256, GEMM_SMEM>>>(x, w_qkv);

    // 2) Fused causal flash attention (Q-tile 128, K-tile 64)
    flash_kernel<<<dim3(TT / 128, BB * HH), 256, FLASH_SMEM>>>();

    // 3) Output projection + bias: [4096,1024] @ [1024,1024]
    gemm_proj_kernel<<<dim3(CC / GBN, MTOT / GBM), 256, GEMM_SMEM>>>(w_proj, b_proj, out);
}

// round 6
// speedup vs baseline: 1.1323x; 1.1132x over previous
#include <cuda_runtime.h>
#include <cstdint>
#include <cstddef>

// Problem constants
#define BB 2
#define TT 2048
#define CC 1024
#define HH 16
#define DD 64
#define MTOT (BB*TT)          // 4096 rows

// ---------------------------------------------------------------------------
// Scratch: exactly 64 MiB total (proven-passing footprint).
//   g_qkv : QKV output [4096][3072]. First 1M floats reused for w_proj^T
//           AFTER flash has consumed g_qkv.
//   g_att : holds w_qkv^T [3072][1024] during QKV GEMM, then overwritten by
//           flash with the attention output [4096][1024].
// ---------------------------------------------------------------------------
__device__ float g_qkv[(size_t)MTOT * 3 * CC];   // 48 MiB
__device__ float g_att[(size_t)MTOT * CC];       // 16 MiB

// ---------------------------------------------------------------------------
// Helpers
// ---------------------------------------------------------------------------
__device__ __forceinline__ float to_tf32(float x) {
    uint32_t y;
    asm("cvt.rna.tf32.f32 %0, %1;" : "=r"(y) : "f"(x));
    return __uint_as_float(y);
}
__device__ __forceinline__ uint32_t cvt_reg(uint32_t r) {
    uint32_t y;
    asm("cvt.rna.tf32.f32 %0, %1;" : "=r"(y) : "f"(__uint_as_float(r)));
    return y;
}

__device__ __forceinline__ void mma8(float d[4], const uint32_t a[4],
                                     uint32_t b0, uint32_t b1) {
    asm volatile(
        "mma.sync.aligned.m16n8k8.row.col.f32.tf32.tf32.f32 "
        "{%0,%1,%2,%3}, {%4,%5,%6,%7}, {%8,%9}, {%0,%1,%2,%3};\n"
        : "+f"(d[0]), "+f"(d[1]), "+f"(d[2]), "+f"(d[3])
        : "r"(a[0]), "r"(a[1]), "r"(a[2]), "r"(a[3]), "r"(b0), "r"(b1));
}

__device__ __forceinline__ void ldsm4(uint32_t& r0, uint32_t& r1,
                                      uint32_t& r2, uint32_t& r3, uint32_t addr) {
    asm volatile("ldmatrix.sync.aligned.m8n8.x4.shared.b16 {%0,%1,%2,%3}, [%4];"
                 : "=r"(r0), "=r"(r1), "=r"(r2), "=r"(r3) : "r"(addr));
}

__device__ __forceinline__ void cp_async16(float* smem_dst, const float* gsrc) {
    uint32_t s = (uint32_t)__cvta_generic_to_shared(smem_dst);
    asm volatile("cp.async.cg.shared.global [%0], [%1], 16;\n"
                 :: "r"(s), "l"(gsrc) : "memory");
}
#define CP_COMMIT() asm volatile("cp.async.commit_group;\n" ::: "memory")
#define CP_WAIT0()  asm volatile("cp.async.wait_group 0;\n" ::: "memory")

// ---------------------------------------------------------------------------
// Transpose + tf32-convert: Wt[n][k] = cvt(W[k][n]).  W is [K][N].
// ---------------------------------------------------------------------------
__device__ __forceinline__ void
transpose_cvt_body(const float* __restrict__ W, float* __restrict__ Wt,
                   int K, int N)
{
    __shared__ float tile[32][33];
    int n0 = blockIdx.x * 32, k0 = blockIdx.y * 32;
    int tx = threadIdx.x, ty = threadIdx.y;     // 32 x 8
#pragma unroll
    for (int i = 0; i < 4; i++)
        tile[ty + 8 * i][tx] = W[(size_t)(k0 + ty + 8 * i) * N + n0 + tx];
    __syncthreads();
#pragma unroll
    for (int i = 0; i < 4; i++)
        Wt[(size_t)(n0 + ty + 8 * i) * K + k0 + tx] = to_tf32(tile[tx][ty + 8 * i]);
}

__global__ void transpose_wqkv_kernel(const float* __restrict__ w_qkv) {
    transpose_cvt_body(w_qkv, g_att, CC, 3 * CC);      // -> g_att (12 MiB used)
}
__global__ void transpose_wproj_kernel(const float* __restrict__ w_proj) {
    transpose_cvt_body(w_proj, g_qkv, CC, CC);          // -> g_qkv[0:1M]
}

// ---------------------------------------------------------------------------
// tf32 GEMM: C[M,N] = A[M,K] @ Bt[N,K]^T (+bias). Both operands k-contiguous.
// cp.async double-buffered, ldmatrix fragments. ACVT: round A frags (rna) in
// registers (A raw fp32). Bt must be pre-converted. Block 128x128, BK=32.
// ---------------------------------------------------------------------------
#define GP 36               // smem pitch (words); 4 mod 32 -> conflict-free
#define GSTG (128*GP)       // words per operand per stage
#define GEMM_SMEM (4*GSTG*4)   // 73728 B

__device__ __forceinline__ void
gemm_stage(const float* __restrict__ src, float* dst, int K, int k0, int tid)
{
#pragma unroll
    for (int t = 0; t < 4; t++) {
        int f = tid + t * 256;
        int row = f >> 3, c4 = f & 7;
        cp_async16(dst + row * GP + c4 * 4, src + (size_t)row * K + k0 + c4 * 4);
    }
}

template<int ACVT, int ROUND>
__device__ __forceinline__ void
gemm_body(const float* __restrict__ A, const float* __restrict__ Bt,
          const float* __restrict__ bias, float* __restrict__ C, int N, int K)
{
    extern __shared__ float sm[];
    float* As = sm;
    float* Bs = sm + 2 * GSTG;

    const int tid  = threadIdx.x;
    const int bm   = blockIdx.y;
    const int bn   = blockIdx.x;
    const int warp = tid >> 5;
    const int lane = tid & 31;
    const int wm   = warp & 3;
    const int wn   = warp >> 2;
    const int g    = lane >> 2;
    const int tir  = lane & 3;

    const int aRow = (lane & 7) + ((lane >> 3) & 1) * 8;
    const int aCol = (lane >> 4) * 4;
    const int bRow = (lane & 7) + (lane >> 4) * 8;
    const int bCol = ((lane >> 3) & 1) * 4;

    const uint32_t aBase = (uint32_t)__cvta_generic_to_shared(As)
                         + (((wm * 32 + aRow) * GP + aCol) << 2);
    const uint32_t bBase = (uint32_t)__cvta_generic_to_shared(Bs)
                         + (((wn * 64 + bRow) * GP + bCol) << 2);

    float acc[2][8][4];
#pragma unroll
    for (int mt = 0; mt < 2; mt++)
#pragma unroll
        for (int nt = 0; nt < 8; nt++)
#pragma unroll
            for (int i = 0; i < 4; i++) acc[mt][nt][i] = 0.0f;

    const float* Ablk = A  + (size_t)(bm * 128) * K;
    const float* Bblk = Bt + (size_t)(bn * 128) * K;
    const int NT = K >> 5;

    gemm_stage(Ablk, As, K, 0, tid);
    gemm_stage(Bblk, Bs, K, 0, tid);
    CP_COMMIT();

    for (int it = 0; it < NT; it++) {
        CP_WAIT0();
        __syncthreads();
        if (it + 1 < NT) {
            int nb = (it + 1) & 1;
            gemm_stage(Ablk, As + nb * GSTG, K, (it + 1) * 32, tid);
            gemm_stage(Bblk, Bs + nb * GSTG, K, (it + 1) * 32, tid);
            CP_COMMIT();
        }
        const uint32_t stg = (uint32_t)((it & 1) * GSTG * 4);

#pragma unroll
        for (int kk = 0; kk < 4; kk++) {
            const uint32_t kb4 = (uint32_t)(kk * 8 * 4);
            uint32_t a[2][4];
            ldsm4(a[0][0], a[0][1], a[0][2], a[0][3], aBase + stg + kb4);
            ldsm4(a[1][0], a[1][1], a[1][2], a[1][3],
                  aBase + stg + kb4 + (16 * GP << 2));
            if (ACVT) {
#pragma unroll
                for (int mt = 0; mt < 2; mt++)
#pragma unroll
                    for (int i = 0; i < 4; i++) a[mt][i] = cvt_reg(a[mt][i]);
            }
            uint32_t b[4][4];
#pragma unroll
            for (int ng = 0; ng < 4; ng++)
                ldsm4(b[ng][0], b[ng][1], b[ng][2], b[ng][3],
                      bBase + stg + kb4 + (uint32_t)(ng * 16 * GP << 2));
#pragma unroll
            for (int ng = 0; ng < 4; ng++) {
                mma8(acc[0][2*ng  ], a[0], b[ng][0], b[ng][1]);
                mma8(acc[0][2*ng+1], a[0], b[ng][2], b[ng][3]);
                mma8(acc[1][2*ng  ], a[1], b[ng][0], b[ng][1]);
                mma8(acc[1][2*ng+1], a[1], b[ng][2], b[ng][3]);
            }
        }
        __syncthreads();
    }

    // ---- epilogue ----
#pragma unroll
    for (int mt = 0; mt < 2; mt++) {
#pragma unroll
        for (int nt = 0; nt < 8; nt++) {
            int row = bm * 128 + wm * 32 + mt * 16 + g;
            int col = bn * 128 + wn * 64 + nt * 8 + tir * 2;
            float bb0 = 0.f, bb1 = 0.f;
            if (bias) { bb0 = bias[col]; bb1 = bias[col + 1]; }
            float v00 = acc[mt][nt][0] + bb0, v01 = acc[mt][nt][1] + bb1;
            float v10 = acc[mt][nt][2] + bb0, v11 = acc[mt][nt][3] + bb1;
            if (ROUND) {
                v00 = to_tf32(v00); v01 = to_tf32(v01);
                v10 = to_tf32(v10); v11 = to_tf32(v11);
            }
            *(float2*)(C + (size_t)row * N + col)       = make_float2(v00, v01);
            *(float2*)(C + (size_t)(row + 8) * N + col) = make_float2(v10, v11);
        }
    }
}

// QKV: A = x (raw fp32 -> rna in registers), B = w_qkv^T in g_att,
//      C = g_qkv (tf32-rounded).
__global__ void __launch_bounds__(256, 2)
gemm_qkv_kernel(const float* __restrict__ x)
{
    gemm_body<1, 1>(x, g_att, nullptr, g_qkv, 3 * CC, CC);
}

// Proj: A = g_att (pre-rounded by flash), B = w_proj^T in g_qkv[0:1M],
//       C = out (fp32 + bias).
__global__ void __launch_bounds__(256, 2)
gemm_proj_kernel(const float* __restrict__ b_proj, float* __restrict__ out)
{
    gemm_body<0, 0>(g_att, g_qkv, b_proj, out, CC, CC);
}

// ---------------------------------------------------------------------------
// Flash attention (causal), tf32 mma, cp.async 2-stage K/V double buffer,
// ldmatrix fragments for Q, K, P (V scalar: k-major layout).
// grid = (T/128, B*H). CTA: 128 q-rows, 8 warps (warp w owns rows w*16..+16).
// g_qkv entries are tf32-rounded already (QKV GEMM epilogue).
// ---------------------------------------------------------------------------
#define FP 68
#define VP 72
#define KSTG (64*FP)
#define VSTG (64*VP)
#define FLASH_SMEM ((2*128*FP + 2*KSTG + 2*VSTG)*4)   // 141312 B

__global__ void __launch_bounds__(256)
flash_kernel()
{
    extern __shared__ float fsm[];
    float* Qs = fsm;
    float* Ps = fsm + 128 * FP;
    float* Ks = fsm + 2 * 128 * FP;
    float* Vs = Ks + 2 * KSTG;

    const float* qkv = g_qkv;
    float* O = g_att;

    const int qb  = (gridDim.x - 1) - blockIdx.x;   // heavy blocks first
    const int bh  = blockIdx.y;
    const int b   = bh >> 4;
    const int h   = bh & 15;
    const int tid = threadIdx.x;
    const int w   = tid >> 5;
    const int lane = tid & 31;
    const int g   = lane >> 2;
    const int tir = lane & 3;

    const int aRow = (lane & 7) + ((lane >> 3) & 1) * 8;
    const int aCol = (lane >> 4) * 4;
    const int bRow = (lane & 7) + (lane >> 4) * 8;
    const int bCol = ((lane >> 3) & 1) * 4;

    const uint32_t qBase = (uint32_t)__cvta_generic_to_shared(Qs)
                         + (((w * 16 + aRow) * FP + aCol) << 2);
    const uint32_t pBase = (uint32_t)__cvta_generic_to_shared(Ps)
                         + (((w * 16 + aRow) * FP + aCol) << 2);
    const uint32_t kBase = (uint32_t)__cvta_generic_to_shared(Ks)
                         + ((bRow * FP + bCol) << 2);

    const float scale = 0.125f;            // 1/sqrt(64), exact power of two
    const size_t rowstride = 3 * CC;       // 3072
    const float* qbase = qkv + (size_t)(b * TT) * rowstride + h * DD;
    const float* kbase = qbase + CC;
    const float* vbase = qbase + 2 * CC;

    const int jmax = 2 * qb + 1;

    // ---- prefetch K/V block 0 ----
#pragma unroll
    for (int t = 0; t < 4; t++) {
        int f = tid + t * 256;
        int row = f >> 4, c4 = f & 15;
        size_t goff = (size_t)row * rowstride + c4 * 4;
        cp_async16(Ks + row * FP + c4 * 4, kbase + goff);
        cp_async16(Vs + row * VP + c4 * 4, vbase + goff);
    }
    CP_COMMIT();

    // ---- load Q tile (128x64); values tf32 already, *0.125 exact ----
#pragma unroll
    for (int t = 0; t < 8; t++) {
        int f   = tid + t * 256;
        int row = f >> 4;
        int c4  = f & 15;
        float4 v = *(const float4*)(qbase + (size_t)(qb * 128 + row) * rowstride + c4 * 4);
        float* dst = &Qs[row * FP + c4 * 4];
        dst[0] = v.x * scale; dst[1] = v.y * scale;
        dst[2] = v.z * scale; dst[3] = v.w * scale;
    }

    float m0 = -1e30f, m1 = -1e30f;
    float l0 = 0.f, l1 = 0.f;
    float o[8][4];
#pragma unroll
    for (int nt = 0; nt < 8; nt++)
#pragma unroll
        for (int i = 0; i < 4; i++) o[nt][i] = 0.f;

    for (int j = 0; j <= jmax; j++) {
        CP_WAIT0();
        __syncthreads();
        if (j + 1 <= jmax) {
            int nb = (j + 1) & 1;
#pragma unroll
            for (int t = 0; t < 4; t++) {
                int f = tid + t * 256;
                int row = f >> 4, c4 = f & 15;
                size_t goff = (size_t)((j + 1) * 64 + row) * rowstride + c4 * 4;
                cp_async16(Ks + nb * KSTG + row * FP + c4 * 4, kbase + goff);
                cp_async16(Vs + nb * VSTG + row * VP + c4 * 4, vbase + goff);
            }
            CP_COMMIT();
        }
        const uint32_t kStg = (uint32_t)((j & 1) * KSTG * 4);
        const float* Vc = Vs + (j & 1) * VSTG;

        // ---- S = (Q*scale) @ K^T : warp computes 16x64 ----
        float s[8][4];
#pragma unroll
        for (int nt = 0; nt < 8; nt++)
#pragma unroll
            for (int i = 0; i < 4; i++) s[nt][i] = 0.f;

#pragma unroll
        for (int kk = 0; kk < 8; kk++) {
            const uint32_t kb4 = (uint32_t)(kk * 8 * 4);
            uint32_t a[4];
            ldsm4(a[0], a[1], a[2], a[3], qBase + kb4);
            uint32_t bk[4][4];
#pragma unroll
            for (int ng = 0; ng < 4; ng++)
                ldsm4(bk[ng][0], bk[ng][1], bk[ng][2], bk[ng][3],
                      kBase + kStg + kb4 + (uint32_t)(ng * 16 * FP << 2));
#pragma unroll
            for (int ng = 0; ng < 4; ng++) {
                mma8(s[2*ng  ], a, bk[ng][0], bk[ng][1]);
                mma8(s[2*ng+1], a, bk[ng][2], bk[ng][3]);
            }
        }

        // ---- causal mask (diagonal-region blocks only) ----
        if (j >= 2 * qb) {
            const int qr0 = qb * 128 + w * 16 + g;
            const int qr1 = qr0 + 8;
            const int jc  = j * 64;
#pragma unroll
            for (int nt = 0; nt < 8; nt++) {
                int c0 = jc + nt * 8 + tir * 2;
                int c1 = c0 + 1;
                if (c0 > qr0) s[nt][0] = -1e30f;
                if (c1 > qr0) s[nt][1] = -1e30f;
                if (c0 > qr1) s[nt][2] = -1e30f;
                if (c1 > qr1) s[nt][3] = -1e30f;
            }
        }

        // ---- online softmax ----
        float rm0 = -1e30f, rm1 = -1e30f;
#pragma unroll
        for (int nt = 0; nt < 8; nt++) {
            rm0 = fmaxf(rm0, fmaxf(s[nt][0], s[nt][1]));
            rm1 = fmaxf(rm1, fmaxf(s[nt][2], s[nt][3]));
        }
        rm0 = fmaxf(rm0, __shfl_xor_sync(0xffffffffu, rm0, 1));
        rm0 = fmaxf(rm0, __shfl_xor_sync(0xffffffffu, rm0, 2));
        rm1 = fmaxf(rm1, __shfl_xor_sync(0xffffffffu, rm1, 1));
        rm1 = fmaxf(rm1, __shfl_xor_sync(0xffffffffu, rm1, 2));

        float nm0 = fmaxf(m0, rm0), nm1 = fmaxf(m1, rm1);
        float cf0 = __expf(m0 - nm0), cf1 = __expf(m1 - nm1);
        m0 = nm0; m1 = nm1;

        float rs0 = 0.f, rs1 = 0.f;
        const int prow = w * 16 + g;
#pragma unroll
        for (int nt = 0; nt < 8; nt++) {
            int c = nt * 8 + tir * 2;
            float p0 = __expf(s[nt][0] - nm0);
            float p1 = __expf(s[nt][1] - nm0);
            float p2 = __expf(s[nt][2] - nm1);
            float p3 = __expf(s[nt][3] - nm1);
            rs0 += p0 + p1;
            rs1 += p2 + p3;
            *(float2*)&Ps[(prow    ) * FP + c] =
                make_float2(to_tf32(p0), to_tf32(p1));
            *(float2*)&Ps[(prow + 8) * FP + c] =
                make_float2(to_tf32(p2), to_tf32(p3));
        }
        rs0 += __shfl_xor_sync(0xffffffffu, rs0, 1);
        rs0 += __shfl_xor_sync(0xffffffffu, rs0, 2);
        rs1 += __shfl_xor_sync(0xffffffffu, rs1, 1);
        rs1 += __shfl_xor_sync(0xffffffffu, rs1, 2);
        l0 = l0 * cf0 + rs0;
        l1 = l1 * cf1 + rs1;

#pragma unroll
        for (int nt = 0; nt < 8; nt++) {
            o[nt][0] *= cf0; o[nt][1] *= cf0;
            o[nt][2] *= cf1; o[nt][3] *= cf1;
        }

        __syncwarp();   // Ps rows are per-warp private; order writes vs reads

        // ---- O += P @ V ----
#pragma unroll
        for (int kk = 0; kk < 8; kk++) {
            const int kb = kk * 8;
            uint32_t a[4];
            ldsm4(a[0], a[1], a[2], a[3], pBase + (uint32_t)(kb << 2));
#pragma unroll
            for (int nt = 0; nt < 8; nt++) {
                uint32_t b0 = __float_as_uint(Vc[(kb + tir    ) * VP + nt * 8 + g]);
                uint32_t b1 = __float_as_uint(Vc[(kb + tir + 4) * VP + nt * 8 + g]);
                mma8(o[nt], a, b0, b1);
            }
        }
        __syncthreads();
    }

    // ---- normalize, round to tf32 (proj GEMM A operand), write [B,T,C] ----
    const float inv0 = 1.f / l0;
    const float inv1 = 1.f / l1;
    const int t0 = qb * 128 + w * 16 + g;
#pragma unroll
    for (int nt = 0; nt < 8; nt++) {
        int d = nt * 8 + tir * 2;
        float2 v0 = make_float2(to_tf32(o[nt][0] * inv0), to_tf32(o[nt][1] * inv0));
        float2 v1 = make_float2(to_tf32(o[nt][2] * inv1), to_tf32(o[nt][3] * inv1));
        *(float2*)(O + (size_t)(b * TT + t0    ) * CC + h * DD + d) = v0;
        *(float2*)(O + (size_t)(b * TT + t0 + 8) * CC + h * DD + d) = v1;
    }
}

// ---------------------------------------------------------------------------
// Launch: transpose wqkv -> g_att | QKV gemm -> g_qkv | flash -> g_att |
//         transpose wproj -> g_qkv[0:1M] | proj gemm -> out
// ---------------------------------------------------------------------------
extern "C" void kernel_launch(void* const* d_in, const int* in_sizes, int n_in,
                              void* d_out, int out_size)
{
    const float* x      = (const float*)d_in[0];
    const float* w_qkv  = (const float*)d_in[1];
    const float* w_proj = (const float*)d_in[2];
    const float* b_proj = (const float*)d_in[3];
    float* out = (float*)d_out;

    cudaFuncSetAttribute(gemm_qkv_kernel,
                         cudaFuncAttributeMaxDynamicSharedMemorySize, GEMM_SMEM);
    cudaFuncSetAttribute(gemm_proj_kernel,
                         cudaFuncAttributeMaxDynamicSharedMemorySize, GEMM_SMEM);
    cudaFuncSetAttribute(flash_kernel,
                         cudaFuncAttributeMaxDynamicSharedMemorySize, FLASH_SMEM);

    // 0) w_qkv [1024][3072] -> w_qkv^T [3072][1024] in g_att
    transpose_wqkv_kernel<<<dim3(3 * CC / 32, CC / 32), dim3(32, 8)>>>(w_qkv);

    // 1) QKV projection (A = x with in-register rna; output tf32-rounded)
    gemm_qkv_kernel<<<dim3(3 * CC / 128, MTOT / 128), 256, GEMM_SMEM>>>(x);

    // 2) Fused causal flash attention: g_qkv -> g_att (overwrites w_qkv^T)
    flash_kernel<<<dim3(TT / 128, BB * HH), 256, FLASH_SMEM>>>();

    // 3) w_proj -> w_proj^T into g_qkv[0:1M] (g_qkv dead after flash)
    transpose_wproj_kernel<<<dim3(CC / 32, CC / 32), dim3(32, 8)>>>(w_proj);

    // 4) Output projection + bias (all operands pre-rounded; no cvt)
    gemm_proj_kernel<<<dim3(CC / 128, MTOT / 128), 256, GEMM_SMEM>>>(b_proj, out);
}